// round 4
// baseline (speedup 1.0000x reference)
#include <cuda_runtime.h>
#include <cstdint>

#define BDIM 8
#define CDIM 256
#define NDIM 4096
#define BT   128   // block tile edge (rows n and cols m)
#define KB   16    // k-chunk depth

// Scratch (allocation-free rule: device globals)
__device__ float g_MT[CDIM * CDIM];            // MT[k][c] = sum_d Wq[d,c] * Wk[d,k]
__device__ float g_Y[BDIM * CDIM * NDIM];      // Y[b][c][m] = sum_k MT[k][c]... (= (Wq^T Wk) X)

// ---------------- helpers ----------------
__device__ __forceinline__ void cp16(uint32_t s, const void* g) {
    asm volatile("cp.async.cg.shared.global [%0], [%1], 16;" :: "r"(s), "l"(g));
}
__device__ __forceinline__ void cp_commit() { asm volatile("cp.async.commit_group;"); }
__device__ __forceinline__ void cp_wait0()  { asm volatile("cp.async.wait_group 0;"); }
__device__ __forceinline__ void cp_wait1()  { asm volatile("cp.async.wait_group 1;"); }

__device__ __forceinline__ unsigned long long dup2(float x) {
    unsigned long long r;
    asm("mov.b64 %0, {%1, %1};" : "=l"(r) : "f"(x));
    return r;
}
__device__ __forceinline__ void ffma2(unsigned long long& d, unsigned long long a, unsigned long long b) {
    asm("fma.rn.f32x2 %0, %1, %2, %0;" : "+l"(d) : "l"(a), "l"(b));
}
__device__ __forceinline__ float lo32(unsigned long long v) { return __uint_as_float((unsigned int)v); }
__device__ __forceinline__ float hi32(unsigned long long v) { return __uint_as_float((unsigned int)(v >> 32)); }

// ---------------- kernel A: MT = (Wq^T Wk)^T fold, MT[k][c] = sum_d Wq[d,c]*Wk[d,k] ----------------
__global__ void mt_kernel(const float* __restrict__ Wq, const float* __restrict__ Wk) {
    __shared__ float Qs[16][16];
    __shared__ float Ks[16][16];
    const int tx = threadIdx.x, ty = threadIdx.y;
    const int c = blockIdx.x * 16 + tx;
    const int k = blockIdx.y * 16 + ty;
    float acc = 0.f;
    for (int d0 = 0; d0 < CDIM; d0 += 16) {
        Qs[ty][tx] = Wq[(d0 + ty) * CDIM + blockIdx.x * 16 + tx];
        Ks[ty][tx] = Wk[(d0 + ty) * CDIM + blockIdx.y * 16 + tx];
        __syncthreads();
#pragma unroll
        for (int dd = 0; dd < 16; dd++) acc += Qs[dd][tx] * Ks[dd][ty];
        __syncthreads();
    }
    g_MT[k * CDIM + c] = acc;
}

// ---------------- kernel B: Y[b] = M @ X[b]  (Y[c,m] = sum_k MT[k][c] * X[k,m]) ----------------
__global__ __launch_bounds__(256, 2) void ymat_kernel(const float* __restrict__ X) {
    const int b  = blockIdx.z;
    const int m0 = blockIdx.x * BT;
    const int c0 = blockIdx.y * BT;
    const float* Xb = X + (size_t)b * CDIM * NDIM;
    float* Yb = g_Y + (size_t)b * CDIM * NDIM;

    __shared__ float As[2][KB][BT];   // MT chunk: [k][c]
    __shared__ float Bs[2][KB][BT];   // X  chunk: [k][m]

    const int tid = threadIdx.x;
    const int tx = tid & 15, ty = tid >> 4;
    const int kk0 = tid >> 5;         // 0..7
    const int c4 = (tid & 31) * 4;    // 0..124

    uint32_t aAddr0 = (uint32_t)__cvta_generic_to_shared(&As[0][kk0][c4]);
    uint32_t bAddr0 = (uint32_t)__cvta_generic_to_shared(&Bs[0][kk0][c4]);
    const uint32_t bufStride = (uint32_t)(KB * BT * 4);
    const uint32_t rowOff = 8 * BT * 4;

    const float* gA0 = g_MT + kk0 * CDIM + c0 + c4;   // stride CDIM per k
    const float* gB0 = Xb + kk0 * NDIM + m0 + c4;     // stride NDIM per k

    // prologue chunk 0
    cp16(aAddr0, gA0);
    cp16(aAddr0 + rowOff, gA0 + 8 * CDIM);
    cp16(bAddr0, gB0);
    cp16(bAddr0 + rowOff, gB0 + 8 * NDIM);
    cp_commit();

    unsigned long long acc[8][4];
#pragma unroll
    for (int i = 0; i < 8; i++)
#pragma unroll
        for (int j = 0; j < 4; j++) acc[i][j] = 0ull;

    const int NKC = CDIM / KB;  // 16
#pragma unroll 1
    for (int kc = 0; kc < NKC; kc++) {
        if (kc + 1 < NKC) {
            uint32_t boff = (uint32_t)((kc + 1) & 1) * bufStride;
            const float* ga = gA0 + (kc + 1) * KB * CDIM;
            const float* gb = gB0 + (kc + 1) * KB * NDIM;
            cp16(aAddr0 + boff, ga);
            cp16(aAddr0 + boff + rowOff, ga + 8 * CDIM);
            cp16(bAddr0 + boff, gb);
            cp16(bAddr0 + boff + rowOff, gb + 8 * NDIM);
            cp_commit();
            cp_wait1();
        } else {
            cp_wait0();
        }
        __syncthreads();
        const float (*Ac)[BT] = As[kc & 1];
        const float (*Bc)[BT] = Bs[kc & 1];
#pragma unroll
        for (int kk = 0; kk < KB; kk++) {
            float4 a0 = *(const float4*)&Ac[kk][ty * 8];
            float4 a1 = *(const float4*)&Ac[kk][ty * 8 + 4];
            ulonglong2 b0 = *(const ulonglong2*)&Bc[kk][tx * 8];
            ulonglong2 b1 = *(const ulonglong2*)&Bc[kk][tx * 8 + 4];
            unsigned long long bp0 = b0.x, bp1 = b0.y, bp2 = b1.x, bp3 = b1.y;
            float av[8] = {a0.x, a0.y, a0.z, a0.w, a1.x, a1.y, a1.z, a1.w};
#pragma unroll
            for (int i = 0; i < 8; i++) {
                unsigned long long ai = dup2(av[i]);
                ffma2(acc[i][0], ai, bp0);
                ffma2(acc[i][1], ai, bp1);
                ffma2(acc[i][2], ai, bp2);
                ffma2(acc[i][3], ai, bp3);
            }
        }
        __syncthreads();
    }
    // write Y tile: rows c0+ty*8+i, cols m0+tx*8..+7
#pragma unroll
    for (int i = 0; i < 8; i++) {
        int c = c0 + ty * 8 + i;
        float4 w0, w1;
        w0.x = lo32(acc[i][0]); w0.y = hi32(acc[i][0]);
        w0.z = lo32(acc[i][1]); w0.w = hi32(acc[i][1]);
        w1.x = lo32(acc[i][2]); w1.y = hi32(acc[i][2]);
        w1.z = lo32(acc[i][3]); w1.w = hi32(acc[i][3]);
        *(float4*)&Yb[(size_t)c * NDIM + m0 + tx * 8]     = w0;
        *(float4*)&Yb[(size_t)c * NDIM + m0 + tx * 8 + 4] = w1;
    }
}

// ---------------- kernel C: flash-style row stats of L = X^T Y, diag softmax, scale X ----------------
__global__ __launch_bounds__(256, 2) void diag_attn_kernel(const float* __restrict__ X,
                                                           float* __restrict__ out) {
    const int b  = blockIdx.y;
    const int n0 = blockIdx.x * BT;
    const float* Xb = X + (size_t)b * CDIM * NDIM;
    const float* Yb = g_Y + (size_t)b * CDIM * NDIM;

    __shared__ float As[2][KB][BT];   // X chunk: [k][n]
    __shared__ float Bs[2][KB][BT];   // Y chunk: [k][m]
    __shared__ float sdiag[BT];
    __shared__ float sfac[BT];

    const int tid = threadIdx.x;
    const int tx = tid & 15, ty = tid >> 4;
    const int kk0 = tid >> 5;
    const int c4 = (tid & 31) * 4;

    uint32_t aAddr0 = (uint32_t)__cvta_generic_to_shared(&As[0][kk0][c4]);
    uint32_t bAddr0 = (uint32_t)__cvta_generic_to_shared(&Bs[0][kk0][c4]);
    const uint32_t bufStride = (uint32_t)(KB * BT * 4);
    const uint32_t rowOff = 8 * BT * 4;

    float mrun[8], srun[8];
#pragma unroll
    for (int i = 0; i < 8; i++) { mrun[i] = -1e30f; srun[i] = 0.f; }

    const float* gA0 = Xb + kk0 * NDIM + n0 + c4;

#pragma unroll 1
    for (int mt = 0; mt < NDIM / BT; mt++) {
        const int m0 = mt * BT;
        const float* gB0 = Yb + kk0 * NDIM + m0 + c4;

        cp16(aAddr0, gA0);
        cp16(aAddr0 + rowOff, gA0 + 8 * NDIM);
        cp16(bAddr0, gB0);
        cp16(bAddr0 + rowOff, gB0 + 8 * NDIM);
        cp_commit();

        unsigned long long acc[8][4];
#pragma unroll
        for (int i = 0; i < 8; i++)
#pragma unroll
            for (int j = 0; j < 4; j++) acc[i][j] = 0ull;

        const int NKC = CDIM / KB;
#pragma unroll 1
        for (int kc = 0; kc < NKC; kc++) {
            if (kc + 1 < NKC) {
                uint32_t boff = (uint32_t)((kc + 1) & 1) * bufStride;
                const float* ga = gA0 + (kc + 1) * KB * NDIM;
                const float* gb = gB0 + (kc + 1) * KB * NDIM;
                cp16(aAddr0 + boff, ga);
                cp16(aAddr0 + boff + rowOff, ga + 8 * NDIM);
                cp16(bAddr0 + boff, gb);
                cp16(bAddr0 + boff + rowOff, gb + 8 * NDIM);
                cp_commit();
                cp_wait1();
            } else {
                cp_wait0();
            }
            __syncthreads();
            const float (*Ac)[BT] = As[kc & 1];
            const float (*Bc)[BT] = Bs[kc & 1];
#pragma unroll
            for (int kk = 0; kk < KB; kk++) {
                float4 a0 = *(const float4*)&Ac[kk][ty * 8];
                float4 a1 = *(const float4*)&Ac[kk][ty * 8 + 4];
                ulonglong2 b0 = *(const ulonglong2*)&Bc[kk][tx * 8];
                ulonglong2 b1 = *(const ulonglong2*)&Bc[kk][tx * 8 + 4];
                unsigned long long bp0 = b0.x, bp1 = b0.y, bp2 = b1.x, bp3 = b1.y;
                float av[8] = {a0.x, a0.y, a0.z, a0.w, a1.x, a1.y, a1.z, a1.w};
#pragma unroll
                for (int i = 0; i < 8; i++) {
                    unsigned long long ai = dup2(av[i]);
                    ffma2(acc[i][0], ai, bp0);
                    ffma2(acc[i][1], ai, bp1);
                    ffma2(acc[i][2], ai, bp2);
                    ffma2(acc[i][3], ai, bp3);
                }
            }
            __syncthreads();
        }

        // capture diagonal (this block's rows == this m-tile's cols when mt == blockIdx.x)
        if (mt == blockIdx.x && tx == ty) {
#pragma unroll
            for (int i = 0; i < 8; i++) {
                unsigned long long p = acc[i][i >> 1];
                sdiag[ty * 8 + i] = (i & 1) ? hi32(p) : lo32(p);
            }
        }

        // online softmax update (per thread over its 8 cols of this tile)
#pragma unroll
        for (int i = 0; i < 8; i++) {
            float v0 = lo32(acc[i][0]), v1 = hi32(acc[i][0]);
            float v2 = lo32(acc[i][1]), v3 = hi32(acc[i][1]);
            float v4 = lo32(acc[i][2]), v5 = hi32(acc[i][2]);
            float v6 = lo32(acc[i][3]), v7 = hi32(acc[i][3]);
            float mx = fmaxf(fmaxf(fmaxf(v0, v1), fmaxf(v2, v3)),
                             fmaxf(fmaxf(v4, v5), fmaxf(v6, v7)));
            float mnew = fmaxf(mrun[i], mx);
            float s = __expf(v0 - mnew) + __expf(v1 - mnew) + __expf(v2 - mnew) + __expf(v3 - mnew)
                    + __expf(v4 - mnew) + __expf(v5 - mnew) + __expf(v6 - mnew) + __expf(v7 - mnew);
            srun[i] = srun[i] * __expf(mrun[i] - mnew) + s;
            mrun[i] = mnew;
        }
    }

    __syncthreads();  // ensure sdiag visible (covers diag tile == last tile case)

    // reduce (max, sumexp) across the 16 tx-lanes sharing each row group
#pragma unroll
    for (int i = 0; i < 8; i++) {
        float m = mrun[i], s = srun[i];
#pragma unroll
        for (int d = 1; d < 16; d <<= 1) {
            float mo = __shfl_xor_sync(0xffffffffu, m, d);
            float so = __shfl_xor_sync(0xffffffffu, s, d);
            float mn = fmaxf(m, mo);
            s = s * __expf(m - mn) + so * __expf(mo - mn);
            m = mn;
        }
        if (tx == 0) sfac[ty * 8 + i] = __expf(sdiag[ty * 8 + i] - m) / s;
    }
    __syncthreads();

    // out[c, n] = X[c, n] * diag[n]
    const float* Xc = Xb + n0 + c4;
    float* Oc = out + (size_t)b * CDIM * NDIM + n0 + c4;
    float4 dd = *(const float4*)&sfac[c4];
#pragma unroll 1
    for (int c = kk0; c < CDIM; c += 8) {
        float4 x = *(const float4*)&Xc[(size_t)c * NDIM];
        x.x *= dd.x; x.y *= dd.y; x.z *= dd.z; x.w *= dd.w;
        *(float4*)&Oc[(size_t)c * NDIM] = x;
    }
}

// ---------------- launch ----------------
extern "C" void kernel_launch(void* const* d_in, const int* in_sizes, int n_in,
                              void* d_out, int out_size) {
    const float* pts = (const float*)d_in[0];
    const float* Wq  = (const float*)d_in[1];
    const float* Wk  = (const float*)d_in[2];
    float* out = (float*)d_out;

    mt_kernel<<<dim3(16, 16), dim3(16, 16)>>>(Wq, Wk);
    ymat_kernel<<<dim3(NDIM / BT, CDIM / BT, BDIM), 256>>>(pts);
    diag_attn_kernel<<<dim3(NDIM / BT, BDIM), 256>>>(pts, out);
}

// round 12
// speedup vs baseline: 1.7137x; 1.7137x over previous
#include <cuda_runtime.h>
#include <cuda_bf16.h>
#include <cstdint>

#define BDIM 8
#define CDIM 256
#define NDIM 4096
#define BT   128
#define KB   16

// ---------------- device scratch (allocation-free rule) ----------------
// NOTE: explicit alignment — bf16 device globals otherwise emit PTX .align 2,
// which makes the 16B cp.async / uint4 accesses formally unaligned.
__device__ __align__(1024) float g_MT[CDIM * CDIM];                         // MT[k][c]
__device__ __align__(1024) __nv_bfloat16 g_Yhi[(size_t)BDIM * NDIM * CDIM]; // Yt hi: [b][m][c]
__device__ __align__(1024) __nv_bfloat16 g_Ylo[(size_t)BDIM * NDIM * CDIM]; // Yt lo
__device__ __align__(1024) __nv_bfloat16 g_Xhi[(size_t)BDIM * NDIM * CDIM]; // Xt hi: [b][n][c]
__device__ __align__(1024) __nv_bfloat16 g_Xlo[(size_t)BDIM * NDIM * CDIM]; // Xt lo

// ---------------- helpers ----------------
__device__ __forceinline__ void cp16(uint32_t s, const void* g) {
    asm volatile("cp.async.cg.shared.global [%0], [%1], 16;" :: "r"(s), "l"(g));
}
__device__ __forceinline__ void cp_commit() { asm volatile("cp.async.commit_group;"); }
__device__ __forceinline__ void cp_wait0()  { asm volatile("cp.async.wait_group 0;"); }
__device__ __forceinline__ void cp_wait1()  { asm volatile("cp.async.wait_group 1;"); }

__device__ __forceinline__ unsigned long long dup2(float x) {
    unsigned long long r;
    asm("mov.b64 %0, {%1, %1};" : "=l"(r) : "f"(x));
    return r;
}
__device__ __forceinline__ void ffma2(unsigned long long& d, unsigned long long a, unsigned long long b) {
    asm("fma.rn.f32x2 %0, %1, %2, %0;" : "+l"(d) : "l"(a), "l"(b));
}
__device__ __forceinline__ float lo32(unsigned long long v) { return __uint_as_float((unsigned int)v); }
__device__ __forceinline__ float hi32(unsigned long long v) { return __uint_as_float((unsigned int)(v >> 32)); }

__device__ __forceinline__ unsigned short f2bf(float x) {
    return __bfloat16_as_ushort(__float2bfloat16(x));
}
__device__ __forceinline__ float bf2f(unsigned short u) {
    __nv_bfloat16_raw r; r.x = u;
    return __bfloat162float(__nv_bfloat16(r));
}
__device__ __forceinline__ uint32_t smem_u32(const void* p) {
    uint32_t a;
    asm("{ .reg .u64 t; cvta.to.shared.u64 t, %1; cvt.u32.u64 %0, t; }" : "=r"(a) : "l"(p));
    return a;
}

// ---------------- tensor-core primitives (plain sm_103-safe: sm_80 era) ----------------
__device__ __forceinline__ void ldsm4(uint32_t* r, uint32_t addr) {
    asm volatile("ldmatrix.sync.aligned.m8n8.x4.shared.b16 {%0,%1,%2,%3}, [%4];"
        : "=r"(r[0]), "=r"(r[1]), "=r"(r[2]), "=r"(r[3]) : "r"(addr));
}
__device__ __forceinline__ void mma_bf16(float* d, const uint32_t* a, const uint32_t* b) {
    asm volatile("mma.sync.aligned.m16n8k16.row.col.f32.bf16.bf16.f32 "
        "{%0,%1,%2,%3}, {%4,%5,%6,%7}, {%8,%9}, {%0,%1,%2,%3};"
        : "+f"(d[0]), "+f"(d[1]), "+f"(d[2]), "+f"(d[3])
        : "r"(a[0]), "r"(a[1]), "r"(a[2]), "r"(a[3]), "r"(b[0]), "r"(b[1]));
}

// ---------------- kernel A: MT fold ----------------
__global__ void mt_kernel(const float* __restrict__ Wq, const float* __restrict__ Wk) {
    __shared__ float Qs[16][16];
    __shared__ float Ks[16][16];
    const int tx = threadIdx.x, ty = threadIdx.y;
    const int c = blockIdx.x * 16 + tx;
    const int k = blockIdx.y * 16 + ty;
    float acc = 0.f;
    for (int d0 = 0; d0 < CDIM; d0 += 16) {
        Qs[ty][tx] = Wq[(d0 + ty) * CDIM + blockIdx.x * 16 + tx];
        Ks[ty][tx] = Wk[(d0 + ty) * CDIM + blockIdx.y * 16 + tx];
        __syncthreads();
#pragma unroll
        for (int dd = 0; dd < 16; dd++) acc += Qs[dd][tx] * Ks[dd][ty];
        __syncthreads();
    }
    g_MT[k * CDIM + c] = acc;
}

// ---------------- kernel A2: Xt split transpose ----------------
__global__ void xt_kernel(const float* __restrict__ X) {
    __shared__ float s[32][33];
    const int b = blockIdx.z;
    const int n0 = blockIdx.x * 32, c0 = blockIdx.y * 32;
    const float* Xb = X + (size_t)b * CDIM * NDIM;
    const int tx = threadIdx.x, ty = threadIdx.y;
#pragma unroll
    for (int i = 0; i < 4; i++)
        s[ty + 8 * i][tx] = Xb[(size_t)(c0 + ty + 8 * i) * NDIM + n0 + tx];
    __syncthreads();
#pragma unroll
    for (int i = 0; i < 4; i++) {
        float v = s[tx][ty + 8 * i];
        unsigned short h = f2bf(v);
        unsigned short l = f2bf(v - bf2f(h));
        size_t off = ((size_t)b * NDIM + n0 + ty + 8 * i) * CDIM + c0 + tx;
        ((unsigned short*)g_Xhi)[off] = h;
        ((unsigned short*)g_Xlo)[off] = l;
    }
}

// ---------------- kernel B: Y = M X, written TRANSPOSED as bf16 hi/lo splits ----------------
__global__ __launch_bounds__(256, 2) void ymat_kernel(const float* __restrict__ X) {
    const int b  = blockIdx.z;
    const int m0 = blockIdx.x * BT;
    const int c0 = blockIdx.y * BT;
    const float* Xb = X + (size_t)b * CDIM * NDIM;

    __shared__ float As[2][KB][BT];
    __shared__ float Bs[2][KB][BT];

    const int tid = threadIdx.x;
    const int tx = tid & 15, ty = tid >> 4;
    const int kk0 = tid >> 5;
    const int c4 = (tid & 31) * 4;

    uint32_t aAddr0 = (uint32_t)__cvta_generic_to_shared(&As[0][kk0][c4]);
    uint32_t bAddr0 = (uint32_t)__cvta_generic_to_shared(&Bs[0][kk0][c4]);
    const uint32_t bufStride = (uint32_t)(KB * BT * 4);
    const uint32_t rowOff = 8 * BT * 4;

    const float* gA0 = g_MT + kk0 * CDIM + c0 + c4;
    const float* gB0 = Xb + kk0 * NDIM + m0 + c4;

    cp16(aAddr0, gA0);
    cp16(aAddr0 + rowOff, gA0 + 8 * CDIM);
    cp16(bAddr0, gB0);
    cp16(bAddr0 + rowOff, gB0 + 8 * NDIM);
    cp_commit();

    unsigned long long acc[8][4];
#pragma unroll
    for (int i = 0; i < 8; i++)
#pragma unroll
        for (int j = 0; j < 4; j++) acc[i][j] = 0ull;

    const int NKC = CDIM / KB;
#pragma unroll 1
    for (int kc = 0; kc < NKC; kc++) {
        if (kc + 1 < NKC) {
            uint32_t boff = (uint32_t)((kc + 1) & 1) * bufStride;
            const float* ga = gA0 + (kc + 1) * KB * CDIM;
            const float* gb = gB0 + (kc + 1) * KB * NDIM;
            cp16(aAddr0 + boff, ga);
            cp16(aAddr0 + boff + rowOff, ga + 8 * CDIM);
            cp16(bAddr0 + boff, gb);
            cp16(bAddr0 + boff + rowOff, gb + 8 * NDIM);
            cp_commit();
            cp_wait1();
        } else {
            cp_wait0();
        }
        __syncthreads();
        const float (*Ac)[BT] = As[kc & 1];
        const float (*Bc)[BT] = Bs[kc & 1];
#pragma unroll
        for (int kk = 0; kk < KB; kk++) {
            float4 a0 = *(const float4*)&Ac[kk][ty * 8];
            float4 a1 = *(const float4*)&Ac[kk][ty * 8 + 4];
            ulonglong2 b0 = *(const ulonglong2*)&Bc[kk][tx * 8];
            ulonglong2 b1 = *(const ulonglong2*)&Bc[kk][tx * 8 + 4];
            unsigned long long bp0 = b0.x, bp1 = b0.y, bp2 = b1.x, bp3 = b1.y;
            float av[8] = {a0.x, a0.y, a0.z, a0.w, a1.x, a1.y, a1.z, a1.w};
#pragma unroll
            for (int i = 0; i < 8; i++) {
                unsigned long long ai = dup2(av[i]);
                ffma2(acc[i][0], ai, bp0);
                ffma2(acc[i][1], ai, bp1);
                ffma2(acc[i][2], ai, bp2);
                ffma2(acc[i][3], ai, bp3);
            }
        }
        __syncthreads();
    }

    // Transposed split write: Yt[b][m][c] hi/lo bf16.
#pragma unroll
    for (int jj = 0; jj < 8; jj++) {
        uint32_t hw[4], lw[4];
#pragma unroll
        for (int p = 0; p < 4; p++) {
            float v0 = (jj & 1) ? hi32(acc[2 * p][jj >> 1])     : lo32(acc[2 * p][jj >> 1]);
            float v1 = (jj & 1) ? hi32(acc[2 * p + 1][jj >> 1]) : lo32(acc[2 * p + 1][jj >> 1]);
            unsigned short h0 = f2bf(v0), h1 = f2bf(v1);
            unsigned short l0 = f2bf(v0 - bf2f(h0)), l1 = f2bf(v1 - bf2f(h1));
            hw[p] = (uint32_t)h0 | ((uint32_t)h1 << 16);
            lw[p] = (uint32_t)l0 | ((uint32_t)l1 << 16);
        }
        size_t row = (size_t)b * NDIM + (m0 + tx * 8 + jj);
        uint4* dh = (uint4*)(g_Yhi + row * CDIM + c0 + ty * 8);
        uint4* dl = (uint4*)(g_Ylo + row * CDIM + c0 + ty * 8);
        *dh = make_uint4(hw[0], hw[1], hw[2], hw[3]);
        *dl = make_uint4(lw[0], lw[1], lw[2], lw[3]);
    }
}

// ---------------- kernel C: mma.sync flash row-stats + diag softmax + scale ----------------
// SMEM: Ahi[128][512B] @0 (64KB), Alo @65536 (64KB),
//       B: @131072 + comp*32768 + stage*16384 (rows 32 x 512B each) (64KB),
//       sdiag @196608 (512B), sfac @197120 (512B). Total 197632.
#define SM_ALO   65536u
#define SM_B     131072u
#define SM_SDIAG 196608u
#define SM_SFAC  197120u
#define SMEM_SZ  197632

__device__ __forceinline__ uint32_t a_addr(uint32_t sb, int comp, int row, int kc, int L) {
    int r = row + (L & 15);
    int kh = (L >> 4) & 1;
    return sb + (uint32_t)comp * SM_ALO + (uint32_t)(r * 512 + ((kc ^ (r & 7)) * 32) + kh * 16);
}
__device__ __forceinline__ uint32_t b_addr(uint32_t sb, int comp, int s, int p, int kc, int L) {
    int r = p * 16 + (L & 7) + (((L >> 4) & 1) << 3);
    int kh = (L >> 3) & 1;
    return sb + SM_B + (uint32_t)comp * 32768u + (uint32_t)s * 16384u +
           (uint32_t)(r * 512 + ((kc ^ (r & 7)) * 32) + kh * 16);
}

__global__ __launch_bounds__(256, 1) void attn_kernel(const float* __restrict__ X,
                                                      float* __restrict__ out) {
    extern __shared__ __align__(1024) char smem[];
    const uint32_t sb = smem_u32(smem);
    const int tid = threadIdx.x;
    const int L = tid & 31;
    const int w = tid >> 5;
    const int b  = blockIdx.y;
    const int n0 = blockIdx.x * 128;

    const float* Xb = X + (size_t)b * CDIM * NDIM;
    float* sdiag = (float*)(smem + SM_SDIAG);
    float* sfac  = (float*)(smem + SM_SFAC);

    // ---- prologue: load A (Xt hi/lo, 128 rows x 512B x2) with swizzle ----
    for (int i = tid; i < 8192; i += 256) {
        int comp = i >> 12;
        int rem = i & 4095;
        int r = rem >> 5, u = rem & 31;
        const __nv_bfloat16* src =
            (comp ? g_Xlo : g_Xhi) + ((size_t)b * NDIM + n0 + r) * CDIM + u * 8;
        uint32_t dst = sb + (uint32_t)comp * SM_ALO +
                       (uint32_t)(r * 512 + (((u >> 1) ^ (r & 7)) * 32) + (u & 1) * 16);
        cp16(dst, src);
    }
    cp_commit();
    cp_wait0();
    __syncthreads();

    // ---- diag: dg[n] = xt_n . yt_n  (hi+lo reconstruction) ----
    if (tid < 128) {
        const int r = tid;
        const uint4* yh = (const uint4*)(g_Yhi + ((size_t)b * NDIM + n0 + r) * CDIM);
        const uint4* yl = (const uint4*)(g_Ylo + ((size_t)b * NDIM + n0 + r) * CDIM);
        float dg = 0.f;
#pragma unroll 4
        for (int u = 0; u < 32; u++) {
            uint32_t off = (uint32_t)(r * 512 + (((u >> 1) ^ (r & 7)) * 32) + (u & 1) * 16);
            uint4 xh = *(const uint4*)(smem + off);
            uint4 xl = *(const uint4*)(smem + SM_ALO + off);
            uint4 vh = yh[u], vl = yl[u];
            const uint32_t* ph = (const uint32_t*)&xh;
            const uint32_t* pl = (const uint32_t*)&xl;
            const uint32_t* qh = (const uint32_t*)&vh;
            const uint32_t* ql = (const uint32_t*)&vl;
#pragma unroll
            for (int ww = 0; ww < 4; ww++) {
                float x0 = bf2f((unsigned short)(ph[ww] & 0xffff)) + bf2f((unsigned short)(pl[ww] & 0xffff));
                float x1 = bf2f((unsigned short)(ph[ww] >> 16))    + bf2f((unsigned short)(pl[ww] >> 16));
                float y0 = bf2f((unsigned short)(qh[ww] & 0xffff)) + bf2f((unsigned short)(ql[ww] & 0xffff));
                float y1 = bf2f((unsigned short)(qh[ww] >> 16))    + bf2f((unsigned short)(ql[ww] >> 16));
                dg = fmaf(x0, y0, dg);
                dg = fmaf(x1, y1, dg);
            }
        }
        sdiag[r] = dg;
    } else {
        // loaders: prefetch B stage 0 (m-tile 0)
        const int lt = tid - 128;
        for (int i = lt; i < 2048; i += 128) {
            int comp = i >> 10;
            int rem = i & 1023;
            int r = rem >> 5, u = rem & 31;
            const __nv_bfloat16* src =
                (comp ? g_Ylo : g_Yhi) + ((size_t)b * NDIM + r) * CDIM + u * 8;
            uint32_t dst = sb + SM_B + (uint32_t)comp * 32768u +
                           (uint32_t)(r * 512 + (((u >> 1) ^ (r & 7)) * 32) + (u & 1) * 16);
            cp16(dst, src);
        }
        cp_commit();
    }

    // ---- mainloop over 128 m-tiles of 32 ----
    const int NIT = NDIM / 32;  // 128
    float mrun[4], srun[4];
#pragma unroll
    for (int j = 0; j < 4; j++) { mrun[j] = -1e30f; srun[j] = 0.f; }

#pragma unroll 1
    for (int it = 0; it < NIT; it++) {
        cp_wait0();          // loaders: stage `it` landed; compute: no-op
        __syncthreads();
        const int s = it & 1;

        if (tid >= 128) {
            // issue stage it+1 into the other buffer (freed by the barrier above)
            if (it + 1 < NIT) {
                const int lt = tid - 128;
                const int mb = (it + 1) * 32;
                const int s2 = (it + 1) & 1;
                for (int i = lt; i < 2048; i += 128) {
                    int comp = i >> 10;
                    int rem = i & 1023;
                    int r = rem >> 5, u = rem & 31;
                    const __nv_bfloat16* src =
                        (comp ? g_Ylo : g_Yhi) + ((size_t)b * NDIM + mb + r) * CDIM + u * 8;
                    uint32_t dst = sb + SM_B + (uint32_t)comp * 32768u + (uint32_t)s2 * 16384u +
                                   (uint32_t)(r * 512 + (((u >> 1) ^ (r & 7)) * 32) + (u & 1) * 16);
                    cp16(dst, src);
                }
                cp_commit();
            }
        } else {
            // ---- compute warp w: D[32n x 32m] ----
            float acc[2][4][4];
#pragma unroll
            for (int a = 0; a < 2; a++)
#pragma unroll
                for (int bt = 0; bt < 4; bt++)
#pragma unroll
                    for (int q = 0; q < 4; q++) acc[a][bt][q] = 0.f;

#pragma unroll 2
            for (int kc = 0; kc < 16; kc++) {
                uint32_t AH[2][4], AL[2][4], BH[2][4], BL[2][4];
                ldsm4(AH[0], a_addr(sb, 0, w * 32,      kc, L));
                ldsm4(AH[1], a_addr(sb, 0, w * 32 + 16, kc, L));
                ldsm4(BH[0], b_addr(sb, 0, s, 0, kc, L));
                ldsm4(BH[1], b_addr(sb, 0, s, 1, kc, L));
#pragma unroll
                for (int a = 0; a < 2; a++)
#pragma unroll
                    for (int bt = 0; bt < 4; bt++)
                        mma_bf16(acc[a][bt], AH[a], &BH[bt >> 1][(bt & 1) * 2]);
                ldsm4(BL[0], b_addr(sb, 1, s, 0, kc, L));
                ldsm4(BL[1], b_addr(sb, 1, s, 1, kc, L));
#pragma unroll
                for (int a = 0; a < 2; a++)
#pragma unroll
                    for (int bt = 0; bt < 4; bt++)
                        mma_bf16(acc[a][bt], AH[a], &BL[bt >> 1][(bt & 1) * 2]);
                ldsm4(AL[0], a_addr(sb, 1, w * 32,      kc, L));
                ldsm4(AL[1], a_addr(sb, 1, w * 32 + 16, kc, L));
#pragma unroll
                for (int a = 0; a < 2; a++)
#pragma unroll
                    for (int bt = 0; bt < 4; bt++)
                        mma_bf16(acc[a][bt], AL[a], &BH[bt >> 1][(bt & 1) * 2]);
            }

            // ---- online softmax update: 4 rows x 8 vals ----
#pragma unroll
            for (int a = 0; a < 2; a++)
#pragma unroll
                for (int h = 0; h < 2; h++) {
                    const int j = a * 2 + h;
                    float v[8];
#pragma unroll
                    for (int bt = 0; bt < 4; bt++) {
                        v[2 * bt]     = acc[a][bt][2 * h];
                        v[2 * bt + 1] = acc[a][bt][2 * h + 1];
                    }
                    float mx = fmaxf(fmaxf(fmaxf(v[0], v[1]), fmaxf(v[2], v[3])),
                                     fmaxf(fmaxf(v[4], v[5]), fmaxf(v[6], v[7])));
                    float mnew = fmaxf(mrun[j], mx);
                    float ss = __expf(v[0] - mnew) + __expf(v[1] - mnew) +
                               __expf(v[2] - mnew) + __expf(v[3] - mnew) +
                               __expf(v[4] - mnew) + __expf(v[5] - mnew) +
                               __expf(v[6] - mnew) + __expf(v[7] - mnew);
                    srun[j] = srun[j] * __expf(mrun[j] - mnew) + ss;
                    mrun[j] = mnew;
                }
        }
    }

    // ---- merge across the 4 lanes sharing each row; write sfac ----
    if (tid < 128) {
#pragma unroll
        for (int j = 0; j < 4; j++) {
            float m = mrun[j], sv = srun[j];
#pragma unroll
            for (int d = 1; d < 4; d <<= 1) {
                float mo = __shfl_xor_sync(0xffffffffu, m, d);
                float so = __shfl_xor_sync(0xffffffffu, sv, d);
                float mn = fmaxf(m, mo);
                sv = sv * __expf(m - mn) + so * __expf(mo - mn);
                m = mn;
            }
            if ((L & 3) == 0) {
                int nl = w * 32 + (j >> 1) * 16 + (j & 1) * 8 + (L >> 2);
                sfac[nl] = __expf(sdiag[nl] - m) / sv;
            }
        }
    }
    __syncthreads();

    // ---- store: out[c][n] = X[c][n] * fac[n] ----
    float* Ob = out + (size_t)b * CDIM * NDIM;
#pragma unroll 1
    for (int idx = tid; idx < 256 * 32; idx += 256) {
        int c = idx >> 5, g = idx & 31;
        float4 f = *(const float4*)&sfac[g * 4];
        float4 x = *(const float4*)(Xb + (size_t)c * NDIM + n0 + g * 4);
        x.x *= f.x; x.y *= f.y; x.z *= f.z; x.w *= f.w;
        *(float4*)(Ob + (size_t)c * NDIM + n0 + g * 4) = x;
    }
}

// ---------------- launch ----------------
extern "C" void kernel_launch(void* const* d_in, const int* in_sizes, int n_in,
                              void* d_out, int out_size) {
    const float* pts = (const float*)d_in[0];
    const float* Wq  = (const float*)d_in[1];
    const float* Wk  = (const float*)d_in[2];
    float* out = (float*)d_out;

    cudaFuncSetAttribute(attn_kernel, cudaFuncAttributeMaxDynamicSharedMemorySize, SMEM_SZ);

    mt_kernel<<<dim3(16, 16), dim3(16, 16)>>>(Wq, Wk);
    xt_kernel<<<dim3(NDIM / 32, CDIM / 32, BDIM), dim3(32, 8)>>>(pts);
    ymat_kernel<<<dim3(NDIM / BT, CDIM / BT, BDIM), 256>>>(pts);
    attn_kernel<<<dim3(NDIM / 128, BDIM), 256, SMEM_SZ>>>(pts, out);
}